// round 4
// baseline (speedup 1.0000x reference)
#include <cuda_runtime.h>
#include <cuda_fp16.h>

typedef unsigned long long u64;
typedef unsigned int u32;

#define NMAX 100000
#define NPAD (NMAX + 128)
#define EMAX 1600000
#define NG   64
#define TM   64

// ---- device scratch ----
__device__ __half g_gh[NPAD * 64];    // g = dinv * (h @ W), fp16 (gather buffer)
__device__ __half g_hbf[NPAD * 64];   // layer activations, fp16 (zero beyond n)
__device__ float  g_dinv[NMAX];
__device__ int    g_cnt[NMAX];
__device__ int    g_rowptr[NMAX + 1];
__device__ int    g_cursor[NMAX];
__device__ int    g_col[EMAX];
__device__ int    g_bsums[1024];
__device__ int    g_gstart[NG];
__device__ int    g_gend[NG];

// ---- f32x2 packed helpers (proved working on this target in R2) ----
static __device__ __forceinline__ u64 pack2(float x, float y) {
    u64 r; asm("mov.b64 %0,{%1,%2};" : "=l"(r) : "f"(x), "f"(y)); return r;
}
static __device__ __forceinline__ void unpack2(u64 v, float& x, float& y) {
    asm("mov.b64 {%0,%1},%2;" : "=f"(x), "=f"(y) : "l"(v));
}
static __device__ __forceinline__ u64 ffma2(u64 a, u64 b, u64 c) {
    u64 d; asm("fma.rn.f32x2 %0,%1,%2,%3;" : "=l"(d) : "l"(a), "l"(b), "l"(c)); return d;
}

// ---------------- setup kernels ----------------

__global__ void init_k(int n) {
    int i = blockIdx.x * blockDim.x + threadIdx.x;
    if (i < n) g_cnt[i] = 0;
    if (i < NG) { g_gstart[i] = 0x7fffffff; g_gend[i] = -1; }
}

// degree count + graph bounds via sorted-batch boundary detection
__global__ void countb_k(const int* __restrict__ dst, const int* __restrict__ batch,
                         int e, int n) {
    int i = blockIdx.x * blockDim.x + threadIdx.x;
    if (i < e) atomicAdd(&g_cnt[dst[i]], 1);
    if (i < n) {
        int b = batch[i];
        if (i == 0) g_gstart[b] = 0;
        else {
            int pb = batch[i - 1];
            if (pb != b) { g_gstart[b] = i; g_gend[pb] = i - 1; }
        }
        if (i == n - 1) g_gend[b] = n - 1;
    }
}

__global__ void scan1_k(int n) {
    int t = threadIdx.x;
    int i = blockIdx.x * 1024 + t;
    int v = (i < n) ? g_cnt[i] : 0;
    if (i < n) g_dinv[i] = rsqrtf((float)v + 1.0f);
    int x = v;
    #pragma unroll
    for (int o = 1; o < 32; o <<= 1) {
        int y = __shfl_up_sync(0xffffffffu, x, o);
        if ((t & 31) >= o) x += y;
    }
    __shared__ int wsum[32];
    if ((t & 31) == 31) wsum[t >> 5] = x;
    __syncthreads();
    if (t < 32) {
        int y = wsum[t];
        int z = y;
        #pragma unroll
        for (int o = 1; o < 32; o <<= 1) {
            int w = __shfl_up_sync(0xffffffffu, z, o);
            if (t >= o) z += w;
        }
        wsum[t] = z - y;
        if (t == 31) g_bsums[blockIdx.x] = z;
    }
    __syncthreads();
    int excl = (x - v) + wsum[t >> 5];
    if (i < n) g_rowptr[i] = excl;
}

__global__ void scan2_k(int nb) {
    int t = threadIdx.x;
    int v = (t < nb) ? g_bsums[t] : 0;
    int x = v;
    #pragma unroll
    for (int o = 1; o < 32; o <<= 1) {
        int y = __shfl_up_sync(0xffffffffu, x, o);
        if ((t & 31) >= o) x += y;
    }
    __shared__ int wsum[32];
    if ((t & 31) == 31) wsum[t >> 5] = x;
    __syncthreads();
    if (t < 32) {
        int y = wsum[t];
        int z = y;
        #pragma unroll
        for (int o = 1; o < 32; o <<= 1) {
            int w = __shfl_up_sync(0xffffffffu, z, o);
            if (t >= o) z += w;
        }
        wsum[t] = z - y;
    }
    __syncthreads();
    int excl = (x - v) + wsum[t >> 5];
    if (t < nb) g_bsums[t] = excl;
}

__global__ void scan3_k(int n, int etot) {
    int i = blockIdx.x * 1024 + threadIdx.x;
    if (i < n) {
        int v = g_rowptr[i] + g_bsums[blockIdx.x];
        g_rowptr[i] = v;
        g_cursor[i] = v;
    }
    if (i == 0) g_rowptr[n] = etot;
}

__global__ void fill_k(const int* __restrict__ src, const int* __restrict__ dst, int e) {
    int i = blockIdx.x * blockDim.x + threadIdx.x;
    if (i < e) {
        int d = dst[i];
        int p = atomicAdd(&g_cursor[d], 1);
        g_col[p] = src[i];
    }
}

// ---------------- register-tiled GEMM ----------------
// CTA: 64-node tile. Thread: 8 rows x 2 cols, row-pair-packed f32x2 accumulators.
// g_gh[r] = fp16( dinv[r] * (A[r] @ W) ).  in_f32 != nullptr -> conv1, else g_hbf.
// xT layout: sX[k*96 + pos(r)], pos(r) = r + 4*(r>>3)  (conflict-free 8-lane access)
__global__ void __launch_bounds__(256) gemm_reg_k(const float* __restrict__ in_f32,
                                                  const float* __restrict__ W, int n) {
    __shared__ float sW[64 * 64];     // W[k][c] row-major, 16KB
    __shared__ float sX[64 * 96];     // transposed padded A tile, 24KB
    __shared__ float sdinv[TM];

    int t = threadIdx.x;
    int tile0 = blockIdx.x * TM;

    // W copy (broadcast-friendly row-major)
    {
        const float4* W4 = (const float4*)W;
        float4* sW4 = (float4*)sW;
        #pragma unroll
        for (int j = t; j < 1024; j += 256) sW4[j] = W4[j];
    }
    if (t < TM) {
        int r = tile0 + t;
        sdinv[t] = (r < n) ? g_dinv[r] : 0.f;
    }

    // A tile load + transpose into sX
    if (in_f32) {
        #pragma unroll
        for (int j = t; j < 1024; j += 256) {       // 64 rows x 16 float4
            int r = j >> 4, q = j & 15;
            int gr = tile0 + r;
            float4 v = make_float4(0.f, 0.f, 0.f, 0.f);
            if (gr < n) v = ((const float4*)(in_f32 + (size_t)gr * 64))[q];
            int p = r + 4 * (r >> 3);
            sX[(4 * q + 0) * 96 + p] = v.x;
            sX[(4 * q + 1) * 96 + p] = v.y;
            sX[(4 * q + 2) * 96 + p] = v.z;
            sX[(4 * q + 3) * 96 + p] = v.w;
        }
    } else {
        const uint4* hp = (const uint4*)(g_hbf + (size_t)tile0 * 64);
        #pragma unroll
        for (int j = t; j < 512; j += 256) {        // 64 rows x 8 uint4 (8 halves each)
            int r = j >> 3, q = j & 7;
            uint4 v = hp[j];                        // rows >= n are zero-filled
            __half2 h0 = *(__half2*)&v.x, h1 = *(__half2*)&v.y;
            __half2 h2 = *(__half2*)&v.z, h3 = *(__half2*)&v.w;
            float2 f0 = __half22float2(h0), f1 = __half22float2(h1);
            float2 f2 = __half22float2(h2), f3 = __half22float2(h3);
            int p = r + 4 * (r >> 3);
            float* col = sX + p;
            col[(8 * q + 0) * 96] = f0.x; col[(8 * q + 1) * 96] = f0.y;
            col[(8 * q + 2) * 96] = f1.x; col[(8 * q + 3) * 96] = f1.y;
            col[(8 * q + 4) * 96] = f2.x; col[(8 * q + 5) * 96] = f2.y;
            col[(8 * q + 6) * 96] = f3.x; col[(8 * q + 7) * 96] = f3.y;
        }
    }
    __syncthreads();

    int rg = t & 7;          // rows 8*rg .. 8*rg+7
    int cg = t >> 3;         // cols 2*cg, 2*cg+1
    const float* xbase = sX + 12 * rg;      // pos(8*rg) = 12*rg
    const float* wbase = sW + 2 * cg;

    u64 acc[8];
    #pragma unroll
    for (int a = 0; a < 8; a++) acc[a] = 0ull;

    #pragma unroll 16
    for (int k = 0; k < 64; k++) {
        const float* xr = xbase + k * 96;
        ulonglong2 xa = *(const ulonglong2*)(xr);      // rowpairs (0,1),(2,3)
        ulonglong2 xb = *(const ulonglong2*)(xr + 4);  // rowpairs (4,5),(6,7)
        float2 w = *(const float2*)(wbase + k * 64);
        u64 w0 = pack2(w.x, w.x);
        u64 w1 = pack2(w.y, w.y);
        acc[0] = ffma2(xa.x, w0, acc[0]);
        acc[1] = ffma2(xa.x, w1, acc[1]);
        acc[2] = ffma2(xa.y, w0, acc[2]);
        acc[3] = ffma2(xa.y, w1, acc[3]);
        acc[4] = ffma2(xb.x, w0, acc[4]);
        acc[5] = ffma2(xb.x, w1, acc[5]);
        acc[6] = ffma2(xb.y, w0, acc[6]);
        acc[7] = ffma2(xb.y, w1, acc[7]);
    }

    // epilogue: scale by dinv, convert fp16, store 2 cols for 8 rows
    #pragma unroll
    for (int rp = 0; rp < 4; rp++) {
        int lr0 = 8 * rg + 2 * rp, lr1 = lr0 + 1;
        float d0 = sdinv[lr0], d1 = sdinv[lr1];
        float e0, o0, e1, o1;
        unpack2(acc[2 * rp + 0], e0, o0);   // col 2cg
        unpack2(acc[2 * rp + 1], e1, o1);   // col 2cg+1
        __half2 h0 = __floats2half2_rn(e0 * d0, e1 * d0);
        __half2 h1 = __floats2half2_rn(o0 * d1, o1 * d1);
        ((__half2*)(g_gh + (size_t)(tile0 + lr0) * 64))[cg] = h0;
        ((__half2*)(g_gh + (size_t)(tile0 + lr1) * 64))[cg] = h1;
    }
}

// ---------------- aggregation ----------------
// one warp per node: h[i] = relu?( dinv[i]*(sum_{j in N(i)} g[j] + g[i]) + bias ), fp16 out
__global__ void __launch_bounds__(256) agg64_k(const float* __restrict__ bias,
                                               int n, int do_relu) {
    int node = (blockIdx.x * blockDim.x + threadIdx.x) >> 5;
    int lane = threadIdx.x & 31;
    if (node >= n) return;

    int beg = g_rowptr[node];
    int end = g_rowptr[node + 1];
    const __half2* g2 = (const __half2*)g_gh;

    float2 acc = __half22float2(g2[(size_t)node * 32 + lane]);   // self term

    int e = beg;
    for (; e + 8 <= end; e += 8) {
        int s0 = __ldg(&g_col[e + 0]);
        int s1 = __ldg(&g_col[e + 1]);
        int s2 = __ldg(&g_col[e + 2]);
        int s3 = __ldg(&g_col[e + 3]);
        int s4 = __ldg(&g_col[e + 4]);
        int s5 = __ldg(&g_col[e + 5]);
        int s6 = __ldg(&g_col[e + 6]);
        int s7 = __ldg(&g_col[e + 7]);
        __half2 v0 = g2[(size_t)s0 * 32 + lane];
        __half2 v1 = g2[(size_t)s1 * 32 + lane];
        __half2 v2 = g2[(size_t)s2 * 32 + lane];
        __half2 v3 = g2[(size_t)s3 * 32 + lane];
        __half2 v4 = g2[(size_t)s4 * 32 + lane];
        __half2 v5 = g2[(size_t)s5 * 32 + lane];
        __half2 v6 = g2[(size_t)s6 * 32 + lane];
        __half2 v7 = g2[(size_t)s7 * 32 + lane];
        float2 f0 = __half22float2(v0), f1 = __half22float2(v1);
        float2 f2 = __half22float2(v2), f3 = __half22float2(v3);
        float2 f4 = __half22float2(v4), f5 = __half22float2(v5);
        float2 f6 = __half22float2(v6), f7 = __half22float2(v7);
        acc.x += ((f0.x + f1.x) + (f2.x + f3.x)) + ((f4.x + f5.x) + (f6.x + f7.x));
        acc.y += ((f0.y + f1.y) + (f2.y + f3.y)) + ((f4.y + f5.y) + (f6.y + f7.y));
    }
    for (; e < end; e++) {
        int s = __ldg(&g_col[e]);
        float2 v = __half22float2(g2[(size_t)s * 32 + lane]);
        acc.x += v.x; acc.y += v.y;
    }

    float di = g_dinv[node];
    float2 b = ((const float2*)bias)[lane];
    float ox = di * acc.x + b.x;
    float oy = di * acc.y + b.y;
    if (do_relu) { ox = fmaxf(ox, 0.f); oy = fmaxf(oy, 0.f); }
    __half2 o2 = __floats2half2_rn(ox, oy);
    ((__half2*)g_hbf)[(size_t)node * 32 + lane] = o2;
}

// ---------------- pooling + head ----------------
__global__ void pool_linear_k(const float* __restrict__ Wl, const float* __restrict__ bl,
                              float* __restrict__ out) {
    int g = blockIdx.x;
    int t = threadIdx.x;          // 256
    int f = t & 63;
    int sub = t >> 6;
    int s = g_gstart[g], en = g_gend[g];

    float acc = 0.f;
    if (s <= en) {
        for (int i = s + sub; i <= en; i += 4)
            acc += __half2float(g_hbf[(size_t)i * 64 + f]);
    }
    __shared__ float sm[256];
    sm[t] = acc;
    __syncthreads();
    if (t < 64) {
        float v = sm[t] + sm[t + 64] + sm[t + 128] + sm[t + 192];
        float cnt = (s <= en) ? (float)(en - s + 1) : 0.f;
        sm[t] = v / fmaxf(cnt, 1.f);
    }
    __syncthreads();
    if (t < 2) {
        float o = bl[t];
        #pragma unroll
        for (int k = 0; k < 64; k++) o += sm[k] * Wl[k * 2 + t];
        out[g * 2 + t] = o;
    }
}

// ---------------- launch ----------------

extern "C" void kernel_launch(void* const* d_in, const int* in_sizes, int n_in,
                              void* d_out, int out_size) {
    const float* x     = (const float*)d_in[0];
    const int*   ei    = (const int*)d_in[1];
    const int*   batch = (const int*)d_in[2];
    const float* W1 = (const float*)d_in[3]; const float* b1 = (const float*)d_in[4];
    const float* W2 = (const float*)d_in[5]; const float* b2 = (const float*)d_in[6];
    const float* W3 = (const float*)d_in[7]; const float* b3 = (const float*)d_in[8];
    const float* Wl = (const float*)d_in[9]; const float* bl = (const float*)d_in[10];

    int n = in_sizes[0] / 64;
    int e = in_sizes[1] / 2;
    const int* src = ei;
    const int* dst = ei + e;

    int nb = (n + 1023) / 1024;
    int me = (e > n) ? e : n;
    int ntile = (n + TM - 1) / TM;

    init_k  <<<(n + 255) / 256, 256>>>(n);
    countb_k<<<(me + 255) / 256, 256>>>(dst, batch, e, n);
    scan1_k <<<nb, 1024>>>(n);
    // gemm1 depends only on dinv (scan1); runs while CSR build finishes
    gemm_reg_k<<<ntile, 256>>>(x, W1, n);
    scan2_k <<<1, 1024>>>(nb);
    scan3_k <<<nb, 1024>>>(n, e);
    fill_k  <<<(e + 255) / 256, 256>>>(src, dst, e);

    agg64_k   <<<(n + 7) / 8, 256>>>(b1, n, 1);
    gemm_reg_k<<<ntile, 256>>>(nullptr, W2, n);
    agg64_k   <<<(n + 7) / 8, 256>>>(b2, n, 1);
    gemm_reg_k<<<ntile, 256>>>(nullptr, W3, n);
    agg64_k   <<<(n + 7) / 8, 256>>>(b3, n, 0);

    pool_linear_k<<<NG, 256>>>(Wl, bl, (float*)d_out);
}

// round 5
// speedup vs baseline: 1.2847x; 1.2847x over previous
#include <cuda_runtime.h>
#include <cuda_fp16.h>

typedef unsigned long long u64;
typedef unsigned int u32;

#define NMAX 100000
#define NPAD (NMAX + 128)
#define EMAX 1600000
#define NG   64
#define GTM  128   // rows per GEMM CTA

// ---- device scratch ----
__device__ __half g_gh[NPAD * 64];    // g = dinv * (h @ W), fp16 (gather buffer)
__device__ __half g_hbf[NPAD * 64];   // layer activations, fp16 (zero beyond n)
__device__ float  g_dinv[NMAX];
__device__ int    g_cnt[NMAX];
__device__ int    g_rowptr[NMAX + 1];
__device__ int    g_cursor[NMAX];
__device__ int    g_col[EMAX];
__device__ int    g_bsums[1024];
__device__ int    g_gstart[NG];
__device__ int    g_gend[NG];

// ---------------- setup kernels ----------------

__global__ void init_k(int n) {
    int i = blockIdx.x * blockDim.x + threadIdx.x;
    if (i < n) g_cnt[i] = 0;
    if (i < NG) { g_gstart[i] = 0x7fffffff; g_gend[i] = -1; }
}

// x (fp32) -> g_hbf (fp16)
__global__ void xcvt_k(const float* __restrict__ x, int n64) {
    int i = blockIdx.x * blockDim.x + threadIdx.x;   // 8 elems per thread
    if (i * 8 >= n64) return;
    const float4* xp = (const float4*)(x) + i * 2;
    float4 a = xp[0], b = xp[1];
    __half2 h0 = __floats2half2_rn(a.x, a.y);
    __half2 h1 = __floats2half2_rn(a.z, a.w);
    __half2 h2 = __floats2half2_rn(b.x, b.y);
    __half2 h3 = __floats2half2_rn(b.z, b.w);
    ((uint4*)g_hbf)[i] = make_uint4(*(u32*)&h0, *(u32*)&h1, *(u32*)&h2, *(u32*)&h3);
}

// degree count + graph bounds via sorted-batch boundary detection
__global__ void countb_k(const int* __restrict__ dst, const int* __restrict__ batch,
                         int e, int n) {
    int i = blockIdx.x * blockDim.x + threadIdx.x;
    if (i < e) atomicAdd(&g_cnt[dst[i]], 1);
    if (i < n) {
        int b = batch[i];
        if (i == 0) g_gstart[b] = 0;
        else {
            int pb = batch[i - 1];
            if (pb != b) { g_gstart[b] = i; g_gend[pb] = i - 1; }
        }
        if (i == n - 1) g_gend[b] = n - 1;
    }
}

__global__ void scan1_k(int n) {
    int t = threadIdx.x;
    int i = blockIdx.x * 1024 + t;
    int v = (i < n) ? g_cnt[i] : 0;
    if (i < n) g_dinv[i] = rsqrtf((float)v + 1.0f);
    int x = v;
    #pragma unroll
    for (int o = 1; o < 32; o <<= 1) {
        int y = __shfl_up_sync(0xffffffffu, x, o);
        if ((t & 31) >= o) x += y;
    }
    __shared__ int wsum[32];
    if ((t & 31) == 31) wsum[t >> 5] = x;
    __syncthreads();
    if (t < 32) {
        int y = wsum[t];
        int z = y;
        #pragma unroll
        for (int o = 1; o < 32; o <<= 1) {
            int w = __shfl_up_sync(0xffffffffu, z, o);
            if (t >= o) z += w;
        }
        wsum[t] = z - y;
        if (t == 31) g_bsums[blockIdx.x] = z;
    }
    __syncthreads();
    int excl = (x - v) + wsum[t >> 5];
    if (i < n) g_rowptr[i] = excl;
}

__global__ void scan2_k(int nb) {
    int t = threadIdx.x;
    int v = (t < nb) ? g_bsums[t] : 0;
    int x = v;
    #pragma unroll
    for (int o = 1; o < 32; o <<= 1) {
        int y = __shfl_up_sync(0xffffffffu, x, o);
        if ((t & 31) >= o) x += y;
    }
    __shared__ int wsum[32];
    if ((t & 31) == 31) wsum[t >> 5] = x;
    __syncthreads();
    if (t < 32) {
        int y = wsum[t];
        int z = y;
        #pragma unroll
        for (int o = 1; o < 32; o <<= 1) {
            int w = __shfl_up_sync(0xffffffffu, z, o);
            if (t >= o) z += w;
        }
        wsum[t] = z - y;
    }
    __syncthreads();
    int excl = (x - v) + wsum[t >> 5];
    if (t < nb) g_bsums[t] = excl;
}

__global__ void scan3_k(int n, int etot) {
    int i = blockIdx.x * 1024 + threadIdx.x;
    if (i < n) {
        int v = g_rowptr[i] + g_bsums[blockIdx.x];
        g_rowptr[i] = v;
        g_cursor[i] = v;
    }
    if (i == 0) g_rowptr[n] = etot;
}

__global__ void fill_k(const int* __restrict__ src, const int* __restrict__ dst, int e) {
    int i = blockIdx.x * blockDim.x + threadIdx.x;
    if (i < e) {
        int d = dst[i];
        int p = atomicAdd(&g_cursor[d], 1);
        g_col[p] = src[i];
    }
}

// ---------------- HFMA2 GEMM ----------------
// CTA: 128 rows x 64 cols, 128 threads; thread: 8 rows x 8 cols.
// xT in smem fp16, 16B-chunk swizzle: chunk(k, rg) at byte k*256 + ((rg^(k&15))<<4).
// w in smem fp16 row-major. acc: half2 over col-pairs, fp32 flush every 32 k.
// g_gh[r] = fp16( dinv[r] * (h[r] @ W) ), reading h from g_hbf (fp16).
__global__ void __launch_bounds__(128, 4) gemm_h2_k(const float* __restrict__ W, int n) {
    __shared__ __align__(16) unsigned char sXT[16384];   // 64 k x 128 halves (swizzled)
    __shared__ __align__(16) __half sWh[4096];           // w[k][c]
    __shared__ float sdinv[GTM];

    int t = threadIdx.x;
    int tile0 = blockIdx.x * GTM;

    // w: fp32 -> fp16
    {
        const float4* W4 = (const float4*)W;
        __half2* wh2 = (__half2*)sWh;
        #pragma unroll
        for (int j = t; j < 1024; j += 128) {
            float4 v = W4[j];
            wh2[2 * j]     = __floats2half2_rn(v.x, v.y);
            wh2[2 * j + 1] = __floats2half2_rn(v.z, v.w);
        }
    }
    if (t < GTM) {
        int r = tile0 + t;
        sdinv[t] = (r < n) ? g_dinv[r] : 0.f;
    }

    // transpose h tile into sXT: thread = row r
    {
        int r = t;
        const uint4* hp = (const uint4*)(g_hbf + (size_t)(tile0 + r) * 64);
        int rc = r >> 3, rb = (r & 7) * 2;
        #pragma unroll
        for (int q = 0; q < 8; q++) {
            uint4 v = hp[q];                 // k = 8q .. 8q+7
            __half h[8];
            *(uint4*)h = v;
            #pragma unroll
            for (int j = 0; j < 8; j++) {
                int k = 8 * q + j;
                *(__half*)(sXT + k * 256 + ((rc ^ (k & 15)) << 4) + rb) = h[j];
            }
        }
    }
    __syncthreads();

    int rg = t & 15;            // row chunk: rows 8*rg .. 8*rg+7
    int cgp = t >> 4;           // col group: cols 8*cgp .. +7 (col-pairs 4*cgp..+3)

    float fac[64];              // [row j][col c] fp32 accumulators
    #pragma unroll
    for (int a = 0; a < 64; a++) fac[a] = 0.f;

    #pragma unroll
    for (int half = 0; half < 2; half++) {
        __half2 acc[32];        // [j][cp]
        #pragma unroll
        for (int a = 0; a < 32; a++) acc[a] = __floats2half2_rn(0.f, 0.f);

        #pragma unroll 8
        for (int kk = 0; kk < 32; kk++) {
            int k = half * 32 + kk;
            uint4 xv = *(const uint4*)(sXT + k * 256 + ((rg ^ (k & 15)) << 4));
            uint4 wv = *(const uint4*)(sWh + (size_t)k * 64 + cgp * 8);
            __half2 w0 = *(__half2*)&wv.x, w1 = *(__half2*)&wv.y;
            __half2 w2 = *(__half2*)&wv.z, w3 = *(__half2*)&wv.w;
            u32 xw[4] = {xv.x, xv.y, xv.z, xv.w};
            #pragma unroll
            for (int p = 0; p < 4; p++) {   // row pair 2p, 2p+1
                __half2 xpair = *(__half2*)&xw[p];
                __half2 xlo = __low2half2(xpair);    // (x_{2p}, x_{2p})
                __half2 xhi = __high2half2(xpair);
                acc[(2 * p) * 4 + 0] = __hfma2(xlo, w0, acc[(2 * p) * 4 + 0]);
                acc[(2 * p) * 4 + 1] = __hfma2(xlo, w1, acc[(2 * p) * 4 + 1]);
                acc[(2 * p) * 4 + 2] = __hfma2(xlo, w2, acc[(2 * p) * 4 + 2]);
                acc[(2 * p) * 4 + 3] = __hfma2(xlo, w3, acc[(2 * p) * 4 + 3]);
                acc[(2 * p + 1) * 4 + 0] = __hfma2(xhi, w0, acc[(2 * p + 1) * 4 + 0]);
                acc[(2 * p + 1) * 4 + 1] = __hfma2(xhi, w1, acc[(2 * p + 1) * 4 + 1]);
                acc[(2 * p + 1) * 4 + 2] = __hfma2(xhi, w2, acc[(2 * p + 1) * 4 + 2]);
                acc[(2 * p + 1) * 4 + 3] = __hfma2(xhi, w3, acc[(2 * p + 1) * 4 + 3]);
            }
        }
        // flush fp16 chunk accumulators into fp32
        #pragma unroll
        for (int j = 0; j < 8; j++)
            #pragma unroll
            for (int cp = 0; cp < 4; cp++) {
                float2 f = __half22float2(acc[j * 4 + cp]);
                fac[j * 8 + 2 * cp]     += f.x;
                fac[j * 8 + 2 * cp + 1] += f.y;
            }
    }
    __syncthreads();    // done reading sXT; reuse as output staging

    // epilogue: scale by dinv, fp16, stage to smem (row r: 128B; chunk swz (cgp + rg) & 7)
    #pragma unroll
    for (int j = 0; j < 8; j++) {
        int r = 8 * rg + j;
        float di = sdinv[r];
        __half2 o[4];
        #pragma unroll
        for (int cp = 0; cp < 4; cp++)
            o[cp] = __floats2half2_rn(fac[j * 8 + 2 * cp] * di, fac[j * 8 + 2 * cp + 1] * di);
        *(uint4*)(sXT + r * 128 + (((cgp + rg) & 7) << 4)) = *(uint4*)o;
    }
    __syncthreads();

    // coalesced copy-out
    #pragma unroll
    for (int i = 0; i < 8; i++) {
        int idx = t + 128 * i;          // 1024 uint4 total
        int row = idx >> 3, q = idx & 7;
        if (tile0 + row < n) {
            uint4 v = *(const uint4*)(sXT + row * 128 + (((q + (row >> 3)) & 7) << 4));
            ((uint4*)(g_gh + (size_t)(tile0 + row) * 64))[q] = v;
        }
    }
}

// ---------------- aggregation ----------------
// one warp per node: h[i] = relu?( dinv[i]*(sum_{j in N(i)} g[j] + g[i]) + bias ), fp16 out
__global__ void __launch_bounds__(256) agg64_k(const float* __restrict__ bias,
                                               int n, int do_relu) {
    int node = (blockIdx.x * blockDim.x + threadIdx.x) >> 5;
    int lane = threadIdx.x & 31;
    if (node >= n) return;

    int beg = g_rowptr[node];
    int end = g_rowptr[node + 1];
    const __half2* g2 = (const __half2*)g_gh;

    float2 acc = __half22float2(g2[(size_t)node * 32 + lane]);   // self term

    int e = beg;
    for (; e + 8 <= end; e += 8) {
        int s0 = __ldg(&g_col[e + 0]);
        int s1 = __ldg(&g_col[e + 1]);
        int s2 = __ldg(&g_col[e + 2]);
        int s3 = __ldg(&g_col[e + 3]);
        int s4 = __ldg(&g_col[e + 4]);
        int s5 = __ldg(&g_col[e + 5]);
        int s6 = __ldg(&g_col[e + 6]);
        int s7 = __ldg(&g_col[e + 7]);
        __half2 v0 = g2[(size_t)s0 * 32 + lane];
        __half2 v1 = g2[(size_t)s1 * 32 + lane];
        __half2 v2 = g2[(size_t)s2 * 32 + lane];
        __half2 v3 = g2[(size_t)s3 * 32 + lane];
        __half2 v4 = g2[(size_t)s4 * 32 + lane];
        __half2 v5 = g2[(size_t)s5 * 32 + lane];
        __half2 v6 = g2[(size_t)s6 * 32 + lane];
        __half2 v7 = g2[(size_t)s7 * 32 + lane];
        float2 f0 = __half22float2(v0), f1 = __half22float2(v1);
        float2 f2 = __half22float2(v2), f3 = __half22float2(v3);
        float2 f4 = __half22float2(v4), f5 = __half22float2(v5);
        float2 f6 = __half22float2(v6), f7 = __half22float2(v7);
        acc.x += ((f0.x + f1.x) + (f2.x + f3.x)) + ((f4.x + f5.x) + (f6.x + f7.x));
        acc.y += ((f0.y + f1.y) + (f2.y + f3.y)) + ((f4.y + f5.y) + (f6.y + f7.y));
    }
    for (; e < end; e++) {
        int s = __ldg(&g_col[e]);
        float2 v = __half22float2(g2[(size_t)s * 32 + lane]);
        acc.x += v.x; acc.y += v.y;
    }

    float di = g_dinv[node];
    float2 b = ((const float2*)bias)[lane];
    float ox = di * acc.x + b.x;
    float oy = di * acc.y + b.y;
    if (do_relu) { ox = fmaxf(ox, 0.f); oy = fmaxf(oy, 0.f); }
    __half2 o2 = __floats2half2_rn(ox, oy);
    ((__half2*)g_hbf)[(size_t)node * 32 + lane] = o2;
}

// ---------------- pooling + head ----------------
__global__ void pool_linear_k(const float* __restrict__ Wl, const float* __restrict__ bl,
                              float* __restrict__ out) {
    int g = blockIdx.x;
    int t = threadIdx.x;          // 256
    int f = t & 63;
    int sub = t >> 6;
    int s = g_gstart[g], en = g_gend[g];

    float acc = 0.f;
    if (s <= en) {
        for (int i = s + sub; i <= en; i += 4)
            acc += __half2float(g_hbf[(size_t)i * 64 + f]);
    }
    __shared__ float sm[256];
    sm[t] = acc;
    __syncthreads();
    if (t < 64) {
        float v = sm[t] + sm[t + 64] + sm[t + 128] + sm[t + 192];
        float cnt = (s <= en) ? (float)(en - s + 1) : 0.f;
        sm[t] = v / fmaxf(cnt, 1.f);
    }
    __syncthreads();
    if (t < 2) {
        float o = bl[t];
        #pragma unroll
        for (int k = 0; k < 64; k++) o += sm[k] * Wl[k * 2 + t];
        out[g * 2 + t] = o;
    }
}

// ---------------- launch ----------------

extern "C" void kernel_launch(void* const* d_in, const int* in_sizes, int n_in,
                              void* d_out, int out_size) {
    const float* x     = (const float*)d_in[0];
    const int*   ei    = (const int*)d_in[1];
    const int*   batch = (const int*)d_in[2];
    const float* W1 = (const float*)d_in[3]; const float* b1 = (const float*)d_in[4];
    const float* W2 = (const float*)d_in[5]; const float* b2 = (const float*)d_in[6];
    const float* W3 = (const float*)d_in[7]; const float* b3 = (const float*)d_in[8];
    const float* Wl = (const float*)d_in[9]; const float* bl = (const float*)d_in[10];

    int n = in_sizes[0] / 64;
    int e = in_sizes[1] / 2;
    const int* src = ei;
    const int* dst = ei + e;

    int nb = (n + 1023) / 1024;
    int me = (e > n) ? e : n;
    int ntile = (n + GTM - 1) / GTM;

    xcvt_k  <<<(n * 8 + 255) / 256, 256>>>(x, n * 64);
    init_k  <<<(n + 255) / 256, 256>>>(n);
    countb_k<<<(me + 255) / 256, 256>>>(dst, batch, e, n);
    scan1_k <<<nb, 1024>>>(n);
    // gemm1 depends only on dinv + g_hbf; runs while CSR build finishes
    gemm_h2_k<<<ntile, 128>>>(W1, n);
    scan2_k <<<1, 1024>>>(nb);
    scan3_k <<<nb, 1024>>>(n, e);
    fill_k  <<<(e + 255) / 256, 256>>>(src, dst, e);

    agg64_k  <<<(n + 7) / 8, 256>>>(b1, n, 1);
    gemm_h2_k<<<ntile, 128>>>(W2, n);
    agg64_k  <<<(n + 7) / 8, 256>>>(b2, n, 1);
    gemm_h2_k<<<ntile, 128>>>(W3, n);
    agg64_k  <<<(n + 7) / 8, 256>>>(b3, n, 0);

    pool_linear_k<<<NG, 256>>>(Wl, bl, (float*)d_out);
}